// round 14
// baseline (speedup 1.0000x reference)
#include <cuda_runtime.h>
#include <cuda_bf16.h>
#include <cuda_fp16.h>
#include <cstdint>
#include <cstddef>

#define N_NODES 50000
#define EMB 256
#define DFEAT 128
#define N_EDGES 800000
#define N_PAIRS 8192
#define MAX_SELF (2 * N_PAIRS)

// ---------------- device scratch (no allocations allowed) ----------------
__device__ __align__(16) float g_h[(size_t)N_NODES * EMB];      // 51.2 MB
__device__ __align__(16) float g_agg[(size_t)N_NODES * EMB];    // 51.2 MB
__device__ float g_deg[N_NODES];
__device__ int g_self_slot[N_NODES];     // -1 = node unused; else self-OT slot
__device__ int g_self_node[MAX_SELF];
__device__ float g_ot_pair[N_PAIRS];
__device__ float g_ot_self[MAX_SELF];
__device__ int g_is64;
__device__ int g_nself;
__device__ int g_nrel;
__device__ int g_pair_idx[2 * N_PAIRS];
__device__ int g_edge_idx[2 * N_EDGES];   // compacted (src,dst) pairs

__device__ __forceinline__ float flog2(float x) {
    float r; asm("lg2.approx.ftz.f32 %0, %1;" : "=f"(r) : "f"(x)); return r;
}
__device__ __forceinline__ unsigned pack2(float a, float b) {
    unsigned r; asm("cvt.rn.f16x2.f32 %0, %1, %2;" : "=r"(r) : "f"(a), "f"(b)); return r;
}
__device__ __forceinline__ unsigned hexp2u(unsigned x) {
    unsigned r; asm("ex2.approx.f16x2 %0, %1;" : "=r"(r) : "r"(x)); return r;
}
__device__ __forceinline__ unsigned hadd2u(unsigned a, unsigned b) {
    unsigned r; asm("add.rn.f16x2 %0, %1, %2;" : "=r"(r) : "r"(a), "r"(b)); return r;
}
__device__ __forceinline__ float hsum2u(unsigned s) {
    float lo, hi;
    asm("{ .reg .f16 l, h;\n\t mov.b32 {l, h}, %2;\n\t"
        " cvt.f32.f16 %0, l;\n\t cvt.f32.f16 %1, h; }"
        : "=f"(lo), "=f"(hi) : "r"(s));
    return lo + hi;
}
__device__ __forceinline__ void red4(float* p, float4 v) {
    asm volatile("red.global.add.v4.f32 [%0], {%1, %2, %3, %4};"
                 :: "l"(p), "f"(v.x), "f"(v.y), "f"(v.z), "f"(v.w) : "memory");
}

// ---------------- kernel 1: init counters / deg / self_slot ----------------
__global__ void zero_kernel() {
    int tid = blockIdx.x * blockDim.x + threadIdx.x;
    int stride = gridDim.x * blockDim.x;
    if (tid == 0) { g_is64 = 1; g_nself = 0; g_nrel = 0; }
    for (int i = tid; i < N_NODES; i += stride) { g_deg[i] = 0.f; g_self_slot[i] = -1; }
}

// ---------------- kernel 1b: detect index dtype ----------------
__global__ void detect_kernel(const long long* __restrict__ pairs) {
    int i = blockIdx.x * blockDim.x + threadIdx.x;
    if (i < 8192) {
        long long v = pairs[i];
        if (v < 0 || v >= N_NODES) atomicAnd(&g_is64, 0);
    }
}

// ---------------- kernel 1c: decode pairs + claim unique self-OT slots ----------------
__global__ void decode_pairs(const void* __restrict__ pairs) {
    int i = blockIdx.x * blockDim.x + threadIdx.x;
    if (i < 2 * N_PAIRS) {
        int v = g_is64 ? (int)((const long long*)pairs)[i]
                       : ((const int*)pairs)[i];
        g_pair_idx[i] = v;
        if (atomicCAS(&g_self_slot[v], -1, -2) == -1) {
            int s = atomicAdd(&g_nself, 1);
            g_self_node[s] = v;
            g_self_slot[v] = s;
        }
    }
}

// ---------------- kernel 1d: zero agg rows of flagged nodes only ----------------
__global__ void zero_agg_kernel() {
    int lane = threadIdx.x & 31;
    int warp = (blockIdx.x * blockDim.x + threadIdx.x) >> 5;
    if (warp >= N_NODES) return;
    if (g_self_slot[warp] == -1) return;
    float4 z = make_float4(0.f, 0.f, 0.f, 0.f);
    float4* a4 = (float4*)(g_agg + (size_t)warp * EMB);
    a4[lane * 2] = z;
    a4[lane * 2 + 1] = z;
}

// ---------------- kernel 1e: decode + compact relevant edges, count deg ----------------
__global__ void decode_edges(const void* __restrict__ ei) {
    int i = blockIdx.x * blockDim.x + threadIdx.x;
    if (i >= N_EDGES) return;
    int dst = g_is64 ? (int)((const long long*)ei)[N_EDGES + i]
                     : ((const int*)ei)[N_EDGES + i];
    if (g_self_slot[dst] == -1) return;
    int src = g_is64 ? (int)((const long long*)ei)[i]
                     : ((const int*)ei)[i];
    int pos = atomicAdd(&g_nrel, 1);
    g_edge_idx[2 * pos] = src;
    g_edge_idx[2 * pos + 1] = dst;
    atomicAdd(&g_deg[dst], 1.0f);
}

// ---------------- kernel 3: h = x @ W (fp32 SGEMM, 128x128 tile, 8x8/thread) ----------------
__global__ __launch_bounds__(256) void gemm_kernel(const float* __restrict__ x,
                                                   const float* __restrict__ W) {
    __shared__ __align__(16) float Xs[16][132];  // [k][row], padded (132*4 % 16 == 0)
    __shared__ __align__(16) float Ws[16][128];  // [k][col]
    int brow = blockIdx.x * 128;
    int bcol = blockIdx.y * 128;
    int tid = threadIdx.x;
    int tx = tid & 15, ty = tid >> 4;

    float acc[8][8];
#pragma unroll
    for (int i = 0; i < 8; i++)
#pragma unroll
        for (int j = 0; j < 8; j++) acc[i][j] = 0.f;

    const float4* x4 = (const float4*)x;
    const float4* W4 = (const float4*)W;

    for (int ks = 0; ks < DFEAT; ks += 16) {
        // X tile: 128 rows x 16 k (512 float4, 2/thread), transposed into Xs
#pragma unroll
        for (int l = 0; l < 2; l++) {
            int i = tid + l * 256;
            int r = i >> 2;          // 0..127
            int kq = i & 3;          // which float4 of the 16-k slice
            int gr = brow + r;
            float4 v = make_float4(0.f, 0.f, 0.f, 0.f);
            if (gr < N_NODES) v = x4[(size_t)gr * (DFEAT / 4) + (ks >> 2) + kq];
            int k = kq << 2;
            Xs[k][r] = v.x; Xs[k + 1][r] = v.y; Xs[k + 2][r] = v.z; Xs[k + 3][r] = v.w;
        }
        // W tile: 16 k x 128 cols (512 float4, 2/thread), direct copy
#pragma unroll
        for (int l = 0; l < 2; l++) {
            int i = tid + l * 256;
            int k = i >> 5;          // 0..15
            int cq = i & 31;         // float4 col index
            ((float4*)Ws[k])[cq] = W4[(size_t)(ks + k) * (EMB / 4) + (bcol >> 2) + cq];
        }
        __syncthreads();
#pragma unroll
        for (int k = 0; k < 16; k++) {
            float4 a0 = *(const float4*)&Xs[k][ty * 8];
            float4 a1 = *(const float4*)&Xs[k][ty * 8 + 4];
            float4 b0 = ((const float4*)Ws[k])[tx * 2];
            float4 b1 = ((const float4*)Ws[k])[tx * 2 + 1];
            float a[8] = {a0.x, a0.y, a0.z, a0.w, a1.x, a1.y, a1.z, a1.w};
            float b[8] = {b0.x, b0.y, b0.z, b0.w, b1.x, b1.y, b1.z, b1.w};
#pragma unroll
            for (int i = 0; i < 8; i++)
#pragma unroll
                for (int j = 0; j < 8; j++)
                    acc[i][j] = fmaf(a[i], b[j], acc[i][j]);
        }
        __syncthreads();
    }
#pragma unroll
    for (int i = 0; i < 8; i++) {
        int gr = brow + ty * 8 + i;
        if (gr < N_NODES) {
            float4 o0 = make_float4(acc[i][0], acc[i][1], acc[i][2], acc[i][3]);
            float4 o1 = make_float4(acc[i][4], acc[i][5], acc[i][6], acc[i][7]);
            float4* dst = (float4*)(g_h + (size_t)gr * EMB + bcol);
            dst[tx * 2] = o0;
            dst[tx * 2 + 1] = o1;
        }
    }
}

// ---------------- kernel 4: aggregation over compacted edges (v4 red) ----------------
__global__ void agg_kernel() {
    int lane = threadIdx.x & 31;
    int warp = (blockIdx.x * blockDim.x + threadIdx.x) >> 5;
    int nwarps = (gridDim.x * blockDim.x) >> 5;
    int nrel = g_nrel;
    for (int e = warp; e < nrel; e += nwarps) {
        int src = g_edge_idx[2 * e];
        int dst = g_edge_idx[2 * e + 1];
        const float4* hs = (const float4*)(g_h + (size_t)src * EMB);
        float* ad = g_agg + (size_t)dst * EMB;
        float4 v0 = hs[lane * 2];
        float4 v1 = hs[lane * 2 + 1];
        red4(ad + lane * 8, v0);
        red4(ad + lane * 8 + 4, v1);
    }
}

// ---------------- kernel 5: Sinkhorn — SOR (omega=1.5) + polish + early exit ----------------
__device__ __forceinline__ void load_point(int node, int lane, float* p) {
    float dg = g_deg[node];
    float invd = 1.0f / fmaxf(dg, 1.0f);
    const float4* h4 = (const float4*)(g_h + (size_t)node * EMB);
    const float4* a4 = (const float4*)(g_agg + (size_t)node * EMB);
#pragma unroll
    for (int q = 0; q < 2; q++) {
        float4 hv = h4[lane * 2 + q];
        float4 av = a4[lane * 2 + q];
        p[q * 4 + 0] = fmaxf(fmaf(av.x, invd, hv.x), 0.f);
        p[q * 4 + 1] = fmaxf(fmaf(av.y, invd, hv.y), 0.f);
        p[q * 4 + 2] = fmaxf(fmaf(av.z, invd, hv.z), 0.f);
        p[q * 4 + 3] = fmaxf(fmaf(av.w, invd, hv.w), 0.f);
    }
}

// LSE update in K-scaled log2 domain (SHFL broadcast, f32 max, f16x2 exp+sum).
__device__ __forceinline__ float lse_update(float vK, const float* C) {
    float u[32];
    float m0 = -1e30f, m1 = -1e30f, m2 = -1e30f, m3 = -1e30f;
#pragma unroll
    for (int j = 0; j < 32; j += 4) {
        u[j]     = __shfl_sync(0xffffffffu, vK, j)     - C[j];     m0 = fmaxf(m0, u[j]);
        u[j + 1] = __shfl_sync(0xffffffffu, vK, j + 1) - C[j + 1]; m1 = fmaxf(m1, u[j + 1]);
        u[j + 2] = __shfl_sync(0xffffffffu, vK, j + 2) - C[j + 2]; m2 = fmaxf(m2, u[j + 2]);
        u[j + 3] = __shfl_sync(0xffffffffu, vK, j + 3) - C[j + 3]; m3 = fmaxf(m3, u[j + 3]);
    }
    float m = fmaxf(fmaxf(m0, m1), fmaxf(m2, m3));
    unsigned s0 = 0u, s1 = 0u, s2 = 0u, s3 = 0u;
#pragma unroll
    for (int j = 0; j < 32; j += 8) {
        s0 = hadd2u(s0, hexp2u(pack2(u[j]     - m, u[j + 1] - m)));
        s1 = hadd2u(s1, hexp2u(pack2(u[j + 2] - m, u[j + 3] - m)));
        s2 = hadd2u(s2, hexp2u(pack2(u[j + 4] - m, u[j + 5] - m)));
        s3 = hadd2u(s3, hexp2u(pack2(u[j + 6] - m, u[j + 7] - m)));
    }
    float S = hsum2u(hadd2u(hadd2u(s0, s1), hadd2u(s2, s3)));
    return 5.0f - m - flog2(S);   // C0*Kc = log2(32) = 5 exactly
}

__global__ __launch_bounds__(32) void sinkhorn_kernel() {
    __shared__ __align__(16) float Xsh[32][8];
    __shared__ __align__(16) float Ysh[32][8];
    int lane = threadIdx.x;
    int wg = blockIdx.x;

    int nx, ny;
    bool is_pair = (wg < N_PAIRS);
    if (is_pair) {
        nx = g_pair_idx[wg];
        ny = g_pair_idx[N_PAIRS + wg];
    } else {
        int s = wg - N_PAIRS;
        if (s >= g_nself) return;
        nx = ny = g_self_node[s];
    }

    float px[8], py[8];
    load_point(nx, lane, px);
    load_point(ny, lane, py);
#pragma unroll
    for (int k = 0; k < 8; k++) { Xsh[lane][k] = px[k]; Ysh[lane][k] = py[k]; }
    __syncwarp();

    const float Kc = 28.85390081777927f;   // log2(e)/eps
    float CK[32], CTK[32];
#pragma unroll
    for (int j = 0; j < 32; j++) {
        float d2 = 1e-12f, e2 = 1e-12f;
#pragma unroll
        for (int k = 0; k < 8; k++) {
            float dx = px[k] - Ysh[j][k]; d2 = fmaf(dx, dx, d2);
            float dy = py[k] - Xsh[j][k]; e2 = fmaf(dy, dy, e2);
        }
        CK[j] = __fsqrt_rn(d2) * Kc;
        CTK[j] = __fsqrt_rn(e2) * Kc;
    }

    // Over-relaxed Sinkhorn (same fixed point), omega=1.5, early exit at
    // TOL=0.10 K-units on relaxed deltas, then one PLAIN polish pair.
    const float TOL = 0.10f;
    const float OMEGA = 1.5f;
    float fK = 0.f, gK = 0.f;
#pragma unroll 1
    for (int it = 0; it < 50; it++) {
        float fp = fK, gp = gK;
        float fn = lse_update(gK, CK);
        fK = fmaf(OMEGA, fn - fK, fK);
        float gn = lse_update(fK, CTK);
        gK = fmaf(OMEGA, gn - gK, gK);
        bool conv = (fabsf(fK - fp) < TOL) && (fabsf(gK - gp) < TOL);
        if (__all_sync(0xffffffffu, conv)) break;
    }
    // plain polish pair
    fK = lse_update(gK, CK);
    gK = lse_update(fK, CTK);

    float sf = fK, sg = gK;
#pragma unroll
    for (int o = 16; o > 0; o >>= 1) {
        sf += __shfl_xor_sync(0xffffffffu, sf, o);
        sg += __shfl_xor_sync(0xffffffffu, sg, o);
    }
    if (lane == 0) {
        // (mean fK + mean gK) / Kc  =  (sf+sg) * eps*ln2 / 32
        float val = (sf + sg) * 0.001083042469624914f;
        if (is_pair) g_ot_pair[wg] = val;
        else g_ot_self[wg - N_PAIRS] = val;
    }
}

// ---------------- kernel 6: final distortion mean ----------------
__global__ void reduce_kernel(const float* __restrict__ gd, float* __restrict__ out) {
    __shared__ float sh[256];
    float s = 0.f;
    for (int b = threadIdx.x; b < N_PAIRS; b += 256) {
        int pa = g_pair_idx[b];
        int pb = g_pair_idx[N_PAIRS + b];
        float self_a = g_ot_self[g_self_slot[pa]];
        float self_b = g_ot_self[g_self_slot[pb]];
        float d = g_ot_pair[b] - 0.5f * (self_a + self_b);
        s += fabsf(d - gd[b]) / gd[b];
    }
    sh[threadIdx.x] = s;
    __syncthreads();
    for (int o = 128; o > 0; o >>= 1) {
        if (threadIdx.x < o) sh[threadIdx.x] += sh[threadIdx.x + o];
        __syncthreads();
    }
    if (threadIdx.x == 0) out[0] = sh[0] / (float)N_PAIRS;
}

// ---------------- launcher ----------------
extern "C" void kernel_launch(void* const* d_in, const int* in_sizes, int n_in,
                              void* d_out, int out_size) {
    const float* x = (const float*)d_in[0];
    const float* W = (const float*)d_in[1];
    const void* ei = d_in[2];
    const void* pairs = d_in[3];
    const float* gd = (const float*)d_in[4];
    float* out = (float*)d_out;

    zero_kernel<<<256, 256>>>();
    detect_kernel<<<32, 256>>>((const long long*)pairs);
    decode_pairs<<<(2 * N_PAIRS + 255) / 256, 256>>>(pairs);
    zero_agg_kernel<<<(N_NODES + 7) / 8, 256>>>();
    decode_edges<<<(N_EDGES + 255) / 256, 256>>>(ei);
    gemm_kernel<<<dim3((N_NODES + 127) / 128, EMB / 128), 256>>>(x, W);
    agg_kernel<<<512, 256>>>();
    sinkhorn_kernel<<<N_PAIRS + MAX_SELF, 32>>>();
    reduce_kernel<<<1, 256>>>(gd, out);
}

// round 15
// speedup vs baseline: 1.0764x; 1.0764x over previous
#include <cuda_runtime.h>
#include <cuda_bf16.h>
#include <cuda_fp16.h>
#include <cstdint>
#include <cstddef>

#define N_NODES 50000
#define EMB 256
#define DFEAT 128
#define N_EDGES 800000
#define N_PAIRS 8192
#define MAX_SELF (2 * N_PAIRS)

// ---------------- device scratch (no allocations allowed) ----------------
__device__ __align__(16) float g_h[(size_t)N_NODES * EMB];      // 51.2 MB
__device__ __align__(16) float g_agg[(size_t)N_NODES * EMB];    // 51.2 MB
__device__ float g_deg[N_NODES];
__device__ int g_self_slot[N_NODES];     // -1 = node unused; else self-OT slot
__device__ int g_self_node[MAX_SELF];
__device__ float g_ot_pair[N_PAIRS];
__device__ float g_ot_self[MAX_SELF];
__device__ int g_is64;
__device__ int g_nself;
__device__ int g_nrel;
__device__ int g_pair_idx[2 * N_PAIRS];
__device__ int g_edge_idx[2 * N_EDGES];   // compacted (src,dst) pairs

__device__ __forceinline__ float flog2(float x) {
    float r; asm("lg2.approx.ftz.f32 %0, %1;" : "=f"(r) : "f"(x)); return r;
}
__device__ __forceinline__ unsigned pack2(float a, float b) {
    unsigned r; asm("cvt.rn.f16x2.f32 %0, %1, %2;" : "=r"(r) : "f"(a), "f"(b)); return r;
}
__device__ __forceinline__ unsigned hexp2u(unsigned x) {
    unsigned r; asm("ex2.approx.f16x2 %0, %1;" : "=r"(r) : "r"(x)); return r;
}
__device__ __forceinline__ unsigned hadd2u(unsigned a, unsigned b) {
    unsigned r; asm("add.rn.f16x2 %0, %1, %2;" : "=r"(r) : "r"(a), "r"(b)); return r;
}
__device__ __forceinline__ float hsum2u(unsigned s) {
    float lo, hi;
    asm("{ .reg .f16 l, h;\n\t mov.b32 {l, h}, %2;\n\t"
        " cvt.f32.f16 %0, l;\n\t cvt.f32.f16 %1, h; }"
        : "=f"(lo), "=f"(hi) : "r"(s));
    return lo + hi;
}
__device__ __forceinline__ void red4(float* p, float4 v) {
    asm volatile("red.global.add.v4.f32 [%0], {%1, %2, %3, %4};"
                 :: "l"(p), "f"(v.x), "f"(v.y), "f"(v.z), "f"(v.w) : "memory");
}

// ---------------- kernel 1: init counters / deg / self_slot ----------------
__global__ void zero_kernel() {
    int tid = blockIdx.x * blockDim.x + threadIdx.x;
    int stride = gridDim.x * blockDim.x;
    if (tid == 0) { g_is64 = 1; g_nself = 0; g_nrel = 0; }
    for (int i = tid; i < N_NODES; i += stride) { g_deg[i] = 0.f; g_self_slot[i] = -1; }
}

// ---------------- kernel 1b: detect index dtype ----------------
__global__ void detect_kernel(const long long* __restrict__ pairs) {
    int i = blockIdx.x * blockDim.x + threadIdx.x;
    if (i < 8192) {
        long long v = pairs[i];
        if (v < 0 || v >= N_NODES) atomicAnd(&g_is64, 0);
    }
}

// ---------------- kernel 1c: decode pairs + claim unique self-OT slots ----------------
__global__ void decode_pairs(const void* __restrict__ pairs) {
    int i = blockIdx.x * blockDim.x + threadIdx.x;
    if (i < 2 * N_PAIRS) {
        int v = g_is64 ? (int)((const long long*)pairs)[i]
                       : ((const int*)pairs)[i];
        g_pair_idx[i] = v;
        if (atomicCAS(&g_self_slot[v], -1, -2) == -1) {
            int s = atomicAdd(&g_nself, 1);
            g_self_node[s] = v;
            g_self_slot[v] = s;
        }
    }
}

// ---------------- kernel 1d: zero agg rows of flagged nodes only ----------------
__global__ void zero_agg_kernel() {
    int lane = threadIdx.x & 31;
    int warp = (blockIdx.x * blockDim.x + threadIdx.x) >> 5;
    if (warp >= N_NODES) return;
    if (g_self_slot[warp] == -1) return;
    float4 z = make_float4(0.f, 0.f, 0.f, 0.f);
    float4* a4 = (float4*)(g_agg + (size_t)warp * EMB);
    a4[lane * 2] = z;
    a4[lane * 2 + 1] = z;
}

// ---------------- kernel 1e: decode + compact relevant edges, count deg ----------------
__global__ void decode_edges(const void* __restrict__ ei) {
    int i = blockIdx.x * blockDim.x + threadIdx.x;
    if (i >= N_EDGES) return;
    int dst = g_is64 ? (int)((const long long*)ei)[N_EDGES + i]
                     : ((const int*)ei)[N_EDGES + i];
    if (g_self_slot[dst] == -1) return;
    int src = g_is64 ? (int)((const long long*)ei)[i]
                     : ((const int*)ei)[i];
    int pos = atomicAdd(&g_nrel, 1);
    g_edge_idx[2 * pos] = src;
    g_edge_idx[2 * pos + 1] = dst;
    atomicAdd(&g_deg[dst], 1.0f);
}

// ---------------- kernel 3: h = x @ W (fp32 SGEMM, 64x64 tile) ----------------
__global__ __launch_bounds__(256) void gemm_kernel(const float* __restrict__ x,
                                                   const float* __restrict__ W) {
    __shared__ __align__(16) float Xs[64][65];
    __shared__ __align__(16) float Ws[64][64];
    int brow = blockIdx.x * 64;
    int bcol = blockIdx.y * 64;
    int tid = threadIdx.x;
    int tx = tid & 15, ty = tid >> 4;

    float acc[4][4];
#pragma unroll
    for (int i = 0; i < 4; i++)
#pragma unroll
        for (int j = 0; j < 4; j++) acc[i][j] = 0.f;

    const float4* x4 = (const float4*)x;
    const float4* W4 = (const float4*)W;

    for (int ks = 0; ks < DFEAT; ks += 64) {
#pragma unroll
        for (int l = 0; l < 4; l++) {
            int i = tid + l * 256;
            int r = i >> 4;
            int kq = i & 15;
            int gr = brow + r;
            float4 v = make_float4(0.f, 0.f, 0.f, 0.f);
            if (gr < N_NODES) v = x4[(size_t)gr * (DFEAT / 4) + (ks >> 2) + kq];
            int k = kq << 2;
            Xs[k][r] = v.x; Xs[k + 1][r] = v.y; Xs[k + 2][r] = v.z; Xs[k + 3][r] = v.w;
        }
#pragma unroll
        for (int l = 0; l < 4; l++) {
            int i = tid + l * 256;
            int k = i >> 4;
            int cq = i & 15;
            float4 v = W4[(size_t)(ks + k) * (EMB / 4) + (bcol >> 2) + cq];
            ((float4*)Ws[k])[cq] = v;
        }
        __syncthreads();
#pragma unroll
        for (int k = 0; k < 64; k++) {
            float a0 = Xs[k][ty * 4 + 0];
            float a1 = Xs[k][ty * 4 + 1];
            float a2 = Xs[k][ty * 4 + 2];
            float a3 = Xs[k][ty * 4 + 3];
            float4 bb = ((float4*)Ws[k])[tx];
            acc[0][0] = fmaf(a0, bb.x, acc[0][0]); acc[0][1] = fmaf(a0, bb.y, acc[0][1]);
            acc[0][2] = fmaf(a0, bb.z, acc[0][2]); acc[0][3] = fmaf(a0, bb.w, acc[0][3]);
            acc[1][0] = fmaf(a1, bb.x, acc[1][0]); acc[1][1] = fmaf(a1, bb.y, acc[1][1]);
            acc[1][2] = fmaf(a1, bb.z, acc[1][2]); acc[1][3] = fmaf(a1, bb.w, acc[1][3]);
            acc[2][0] = fmaf(a2, bb.x, acc[2][0]); acc[2][1] = fmaf(a2, bb.y, acc[2][1]);
            acc[2][2] = fmaf(a2, bb.z, acc[2][2]); acc[2][3] = fmaf(a2, bb.w, acc[2][3]);
            acc[3][0] = fmaf(a3, bb.x, acc[3][0]); acc[3][1] = fmaf(a3, bb.y, acc[3][1]);
            acc[3][2] = fmaf(a3, bb.z, acc[3][2]); acc[3][3] = fmaf(a3, bb.w, acc[3][3]);
        }
        __syncthreads();
    }
#pragma unroll
    for (int i = 0; i < 4; i++) {
        int gr = brow + ty * 4 + i;
        if (gr < N_NODES) {
            float4 o = make_float4(acc[i][0], acc[i][1], acc[i][2], acc[i][3]);
            ((float4*)(g_h + (size_t)gr * EMB + bcol))[tx] = o;
        }
    }
}

// ---------------- kernel 4: aggregation over compacted edges (v4 red) ----------------
__global__ void agg_kernel() {
    int lane = threadIdx.x & 31;
    int warp = (blockIdx.x * blockDim.x + threadIdx.x) >> 5;
    int nwarps = (gridDim.x * blockDim.x) >> 5;
    int nrel = g_nrel;
    for (int e = warp; e < nrel; e += nwarps) {
        int src = g_edge_idx[2 * e];
        int dst = g_edge_idx[2 * e + 1];
        const float4* hs = (const float4*)(g_h + (size_t)src * EMB);
        float* ad = g_agg + (size_t)dst * EMB;
        float4 v0 = hs[lane * 2];
        float4 v1 = hs[lane * 2 + 1];
        red4(ad + lane * 8, v0);
        red4(ad + lane * 8 + 4, v1);
    }
}

// ---------------- kernel 5: Sinkhorn — SOR (omega=1.5) + polish + early exit ----------------
__device__ __forceinline__ void load_point(int node, int lane, float* p) {
    float dg = g_deg[node];
    float invd = 1.0f / fmaxf(dg, 1.0f);
    const float4* h4 = (const float4*)(g_h + (size_t)node * EMB);
    const float4* a4 = (const float4*)(g_agg + (size_t)node * EMB);
#pragma unroll
    for (int q = 0; q < 2; q++) {
        float4 hv = h4[lane * 2 + q];
        float4 av = a4[lane * 2 + q];
        p[q * 4 + 0] = fmaxf(fmaf(av.x, invd, hv.x), 0.f);
        p[q * 4 + 1] = fmaxf(fmaf(av.y, invd, hv.y), 0.f);
        p[q * 4 + 2] = fmaxf(fmaf(av.z, invd, hv.z), 0.f);
        p[q * 4 + 3] = fmaxf(fmaf(av.w, invd, hv.w), 0.f);
    }
}

// LSE update in K-scaled log2 domain (SHFL broadcast, f32 max, f16x2 exp+sum).
__device__ __forceinline__ float lse_update(float vK, const float* C) {
    float u[32];
    float m0 = -1e30f, m1 = -1e30f, m2 = -1e30f, m3 = -1e30f;
#pragma unroll
    for (int j = 0; j < 32; j += 4) {
        u[j]     = __shfl_sync(0xffffffffu, vK, j)     - C[j];     m0 = fmaxf(m0, u[j]);
        u[j + 1] = __shfl_sync(0xffffffffu, vK, j + 1) - C[j + 1]; m1 = fmaxf(m1, u[j + 1]);
        u[j + 2] = __shfl_sync(0xffffffffu, vK, j + 2) - C[j + 2]; m2 = fmaxf(m2, u[j + 2]);
        u[j + 3] = __shfl_sync(0xffffffffu, vK, j + 3) - C[j + 3]; m3 = fmaxf(m3, u[j + 3]);
    }
    float m = fmaxf(fmaxf(m0, m1), fmaxf(m2, m3));
    unsigned s0 = 0u, s1 = 0u, s2 = 0u, s3 = 0u;
#pragma unroll
    for (int j = 0; j < 32; j += 8) {
        s0 = hadd2u(s0, hexp2u(pack2(u[j]     - m, u[j + 1] - m)));
        s1 = hadd2u(s1, hexp2u(pack2(u[j + 2] - m, u[j + 3] - m)));
        s2 = hadd2u(s2, hexp2u(pack2(u[j + 4] - m, u[j + 5] - m)));
        s3 = hadd2u(s3, hexp2u(pack2(u[j + 6] - m, u[j + 7] - m)));
    }
    float S = hsum2u(hadd2u(hadd2u(s0, s1), hadd2u(s2, s3)));
    return 5.0f - m - flog2(S);   // C0*Kc = log2(32) = 5 exactly
}

__global__ __launch_bounds__(32) void sinkhorn_kernel() {
    __shared__ __align__(16) float Xsh[32][8];
    __shared__ __align__(16) float Ysh[32][8];
    int lane = threadIdx.x;
    int wg = blockIdx.x;

    int nx, ny;
    bool is_pair = (wg < N_PAIRS);
    if (is_pair) {
        nx = g_pair_idx[wg];
        ny = g_pair_idx[N_PAIRS + wg];
    } else {
        int s = wg - N_PAIRS;
        if (s >= g_nself) return;
        nx = ny = g_self_node[s];
    }

    float px[8], py[8];
    load_point(nx, lane, px);
    load_point(ny, lane, py);
#pragma unroll
    for (int k = 0; k < 8; k++) { Xsh[lane][k] = px[k]; Ysh[lane][k] = py[k]; }
    __syncwarp();

    const float Kc = 28.85390081777927f;   // log2(e)/eps
    float CK[32], CTK[32];
#pragma unroll
    for (int j = 0; j < 32; j++) {
        float d2 = 1e-12f, e2 = 1e-12f;
#pragma unroll
        for (int k = 0; k < 8; k++) {
            float dx = px[k] - Ysh[j][k]; d2 = fmaf(dx, dx, d2);
            float dy = py[k] - Xsh[j][k]; e2 = fmaf(dy, dy, e2);
        }
        CK[j] = __fsqrt_rn(d2) * Kc;
        CTK[j] = __fsqrt_rn(e2) * Kc;
    }

    // Over-relaxed Sinkhorn (same fixed point), omega=1.5, early exit at
    // TOL=0.14 K-units on relaxed deltas, then one PLAIN polish pair so the
    // returned (f,g) are mutually consistent (second-order-accurate value).
    const float TOL = 0.14f;
    const float OMEGA = 1.5f;
    float fK = 0.f, gK = 0.f;
#pragma unroll 1
    for (int it = 0; it < 50; it++) {
        float fp = fK, gp = gK;
        float fn = lse_update(gK, CK);
        fK = fmaf(OMEGA, fn - fK, fK);
        float gn = lse_update(fK, CTK);
        gK = fmaf(OMEGA, gn - gK, gK);
        bool conv = (fabsf(fK - fp) < TOL) && (fabsf(gK - gp) < TOL);
        if (__all_sync(0xffffffffu, conv)) break;
    }
    // plain polish pair
    fK = lse_update(gK, CK);
    gK = lse_update(fK, CTK);

    float sf = fK, sg = gK;
#pragma unroll
    for (int o = 16; o > 0; o >>= 1) {
        sf += __shfl_xor_sync(0xffffffffu, sf, o);
        sg += __shfl_xor_sync(0xffffffffu, sg, o);
    }
    if (lane == 0) {
        // (mean fK + mean gK) / Kc  =  (sf+sg) * eps*ln2 / 32
        float val = (sf + sg) * 0.001083042469624914f;
        if (is_pair) g_ot_pair[wg] = val;
        else g_ot_self[wg - N_PAIRS] = val;
    }
}

// ---------------- kernel 6: final distortion mean ----------------
__global__ void reduce_kernel(const float* __restrict__ gd, float* __restrict__ out) {
    __shared__ float sh[256];
    float s = 0.f;
    for (int b = threadIdx.x; b < N_PAIRS; b += 256) {
        int pa = g_pair_idx[b];
        int pb = g_pair_idx[N_PAIRS + b];
        float self_a = g_ot_self[g_self_slot[pa]];
        float self_b = g_ot_self[g_self_slot[pb]];
        float d = g_ot_pair[b] - 0.5f * (self_a + self_b);
        s += fabsf(d - gd[b]) / gd[b];
    }
    sh[threadIdx.x] = s;
    __syncthreads();
    for (int o = 128; o > 0; o >>= 1) {
        if (threadIdx.x < o) sh[threadIdx.x] += sh[threadIdx.x + o];
        __syncthreads();
    }
    if (threadIdx.x == 0) out[0] = sh[0] / (float)N_PAIRS;
}

// ---------------- launcher ----------------
extern "C" void kernel_launch(void* const* d_in, const int* in_sizes, int n_in,
                              void* d_out, int out_size) {
    const float* x = (const float*)d_in[0];
    const float* W = (const float*)d_in[1];
    const void* ei = d_in[2];
    const void* pairs = d_in[3];
    const float* gd = (const float*)d_in[4];
    float* out = (float*)d_out;

    zero_kernel<<<256, 256>>>();
    detect_kernel<<<32, 256>>>((const long long*)pairs);
    decode_pairs<<<(2 * N_PAIRS + 255) / 256, 256>>>(pairs);
    zero_agg_kernel<<<(N_NODES + 7) / 8, 256>>>();
    decode_edges<<<(N_EDGES + 255) / 256, 256>>>(ei);
    gemm_kernel<<<dim3((N_NODES + 63) / 64, EMB / 64), 256>>>(x, W);
    agg_kernel<<<512, 256>>>();
    sinkhorn_kernel<<<N_PAIRS + MAX_SELF, 32>>>();
    reduce_kernel<<<1, 256>>>(gd, out);
}

// round 16
// speedup vs baseline: 1.1055x; 1.0270x over previous
#include <cuda_runtime.h>
#include <cuda_bf16.h>
#include <cuda_fp16.h>
#include <cstdint>
#include <cstddef>

#define N_NODES 50000
#define EMB 256
#define DFEAT 128
#define N_EDGES 800000
#define N_PAIRS 8192
#define MAX_SELF (2 * N_PAIRS)

// ---------------- device scratch (no allocations allowed) ----------------
__device__ __align__(16) float g_h[(size_t)N_NODES * EMB];      // 51.2 MB
__device__ __align__(16) float g_agg[(size_t)N_NODES * EMB];    // 51.2 MB
__device__ float g_deg[N_NODES];
__device__ int g_self_slot[N_NODES];     // -1 = node unused; else self-OT slot
__device__ int g_self_node[MAX_SELF];
__device__ float g_ot_pair[N_PAIRS];
__device__ float g_ot_self[MAX_SELF];
__device__ int g_is64;
__device__ int g_nself;
__device__ int g_nrel;
__device__ int g_pair_idx[2 * N_PAIRS];
__device__ int g_edge_idx[2 * N_EDGES];   // compacted (src,dst) pairs

__device__ __forceinline__ float flog2(float x) {
    float r; asm("lg2.approx.ftz.f32 %0, %1;" : "=f"(r) : "f"(x)); return r;
}
__device__ __forceinline__ unsigned pack2(float a, float b) {
    unsigned r; asm("cvt.rn.f16x2.f32 %0, %1, %2;" : "=r"(r) : "f"(a), "f"(b)); return r;
}
__device__ __forceinline__ unsigned hexp2u(unsigned x) {
    unsigned r; asm("ex2.approx.f16x2 %0, %1;" : "=r"(r) : "r"(x)); return r;
}
__device__ __forceinline__ unsigned hadd2u(unsigned a, unsigned b) {
    unsigned r; asm("add.rn.f16x2 %0, %1, %2;" : "=r"(r) : "r"(a), "r"(b)); return r;
}
__device__ __forceinline__ float hsum2u(unsigned s) {
    float lo, hi;
    asm("{ .reg .f16 l, h;\n\t mov.b32 {l, h}, %2;\n\t"
        " cvt.f32.f16 %0, l;\n\t cvt.f32.f16 %1, h; }"
        : "=f"(lo), "=f"(hi) : "r"(s));
    return lo + hi;
}
__device__ __forceinline__ void red4(float* p, float4 v) {
    asm volatile("red.global.add.v4.f32 [%0], {%1, %2, %3, %4};"
                 :: "l"(p), "f"(v.x), "f"(v.y), "f"(v.z), "f"(v.w) : "memory");
}

// ---------------- kernel 1: init counters / deg / self_slot ----------------
__global__ void zero_kernel() {
    int tid = blockIdx.x * blockDim.x + threadIdx.x;
    int stride = gridDim.x * blockDim.x;
    if (tid == 0) { g_is64 = 1; g_nself = 0; g_nrel = 0; }
    for (int i = tid; i < N_NODES; i += stride) { g_deg[i] = 0.f; g_self_slot[i] = -1; }
}

// ---------------- kernel 1b: detect index dtype ----------------
__global__ void detect_kernel(const long long* __restrict__ pairs) {
    int i = blockIdx.x * blockDim.x + threadIdx.x;
    if (i < 8192) {
        long long v = pairs[i];
        if (v < 0 || v >= N_NODES) atomicAnd(&g_is64, 0);
    }
}

// ---------------- kernel 1c: decode pairs + claim unique self-OT slots ----------------
__global__ void decode_pairs(const void* __restrict__ pairs) {
    int i = blockIdx.x * blockDim.x + threadIdx.x;
    if (i < 2 * N_PAIRS) {
        int v = g_is64 ? (int)((const long long*)pairs)[i]
                       : ((const int*)pairs)[i];
        g_pair_idx[i] = v;
        if (atomicCAS(&g_self_slot[v], -1, -2) == -1) {
            int s = atomicAdd(&g_nself, 1);
            g_self_node[s] = v;
            g_self_slot[v] = s;
        }
    }
}

// ---------------- kernel 1d: zero agg rows of flagged nodes only ----------------
__global__ void zero_agg_kernel() {
    int lane = threadIdx.x & 31;
    int warp = (blockIdx.x * blockDim.x + threadIdx.x) >> 5;
    if (warp >= N_NODES) return;
    if (g_self_slot[warp] == -1) return;
    float4 z = make_float4(0.f, 0.f, 0.f, 0.f);
    float4* a4 = (float4*)(g_agg + (size_t)warp * EMB);
    a4[lane * 2] = z;
    a4[lane * 2 + 1] = z;
}

// ---------------- kernel 1e: decode + compact relevant edges, count deg ----------------
__global__ void decode_edges(const void* __restrict__ ei) {
    int i = blockIdx.x * blockDim.x + threadIdx.x;
    if (i >= N_EDGES) return;
    int dst = g_is64 ? (int)((const long long*)ei)[N_EDGES + i]
                     : ((const int*)ei)[N_EDGES + i];
    if (g_self_slot[dst] == -1) return;
    int src = g_is64 ? (int)((const long long*)ei)[i]
                     : ((const int*)ei)[i];
    int pos = atomicAdd(&g_nrel, 1);
    g_edge_idx[2 * pos] = src;
    g_edge_idx[2 * pos + 1] = dst;
    atomicAdd(&g_deg[dst], 1.0f);
}

// ---------------- kernel 3: h = x @ W (fp32 SGEMM, 64x64 tile) ----------------
__global__ __launch_bounds__(256) void gemm_kernel(const float* __restrict__ x,
                                                   const float* __restrict__ W) {
    __shared__ __align__(16) float Xs[64][65];
    __shared__ __align__(16) float Ws[64][64];
    int brow = blockIdx.x * 64;
    int bcol = blockIdx.y * 64;
    int tid = threadIdx.x;
    int tx = tid & 15, ty = tid >> 4;

    float acc[4][4];
#pragma unroll
    for (int i = 0; i < 4; i++)
#pragma unroll
        for (int j = 0; j < 4; j++) acc[i][j] = 0.f;

    const float4* x4 = (const float4*)x;
    const float4* W4 = (const float4*)W;

    for (int ks = 0; ks < DFEAT; ks += 64) {
#pragma unroll
        for (int l = 0; l < 4; l++) {
            int i = tid + l * 256;
            int r = i >> 4;
            int kq = i & 15;
            int gr = brow + r;
            float4 v = make_float4(0.f, 0.f, 0.f, 0.f);
            if (gr < N_NODES) v = x4[(size_t)gr * (DFEAT / 4) + (ks >> 2) + kq];
            int k = kq << 2;
            Xs[k][r] = v.x; Xs[k + 1][r] = v.y; Xs[k + 2][r] = v.z; Xs[k + 3][r] = v.w;
        }
#pragma unroll
        for (int l = 0; l < 4; l++) {
            int i = tid + l * 256;
            int k = i >> 4;
            int cq = i & 15;
            float4 v = W4[(size_t)(ks + k) * (EMB / 4) + (bcol >> 2) + cq];
            ((float4*)Ws[k])[cq] = v;
        }
        __syncthreads();
#pragma unroll
        for (int k = 0; k < 64; k++) {
            float a0 = Xs[k][ty * 4 + 0];
            float a1 = Xs[k][ty * 4 + 1];
            float a2 = Xs[k][ty * 4 + 2];
            float a3 = Xs[k][ty * 4 + 3];
            float4 bb = ((float4*)Ws[k])[tx];
            acc[0][0] = fmaf(a0, bb.x, acc[0][0]); acc[0][1] = fmaf(a0, bb.y, acc[0][1]);
            acc[0][2] = fmaf(a0, bb.z, acc[0][2]); acc[0][3] = fmaf(a0, bb.w, acc[0][3]);
            acc[1][0] = fmaf(a1, bb.x, acc[1][0]); acc[1][1] = fmaf(a1, bb.y, acc[1][1]);
            acc[1][2] = fmaf(a1, bb.z, acc[1][2]); acc[1][3] = fmaf(a1, bb.w, acc[1][3]);
            acc[2][0] = fmaf(a2, bb.x, acc[2][0]); acc[2][1] = fmaf(a2, bb.y, acc[2][1]);
            acc[2][2] = fmaf(a2, bb.z, acc[2][2]); acc[2][3] = fmaf(a2, bb.w, acc[2][3]);
            acc[3][0] = fmaf(a3, bb.x, acc[3][0]); acc[3][1] = fmaf(a3, bb.y, acc[3][1]);
            acc[3][2] = fmaf(a3, bb.z, acc[3][2]); acc[3][3] = fmaf(a3, bb.w, acc[3][3]);
        }
        __syncthreads();
    }
#pragma unroll
    for (int i = 0; i < 4; i++) {
        int gr = brow + ty * 4 + i;
        if (gr < N_NODES) {
            float4 o = make_float4(acc[i][0], acc[i][1], acc[i][2], acc[i][3]);
            ((float4*)(g_h + (size_t)gr * EMB + bcol))[tx] = o;
        }
    }
}

// ---------------- kernel 4: aggregation over compacted edges (v4 red) ----------------
__global__ void agg_kernel() {
    int lane = threadIdx.x & 31;
    int warp = (blockIdx.x * blockDim.x + threadIdx.x) >> 5;
    int nwarps = (gridDim.x * blockDim.x) >> 5;
    int nrel = g_nrel;
    for (int e = warp; e < nrel; e += nwarps) {
        int src = g_edge_idx[2 * e];
        int dst = g_edge_idx[2 * e + 1];
        const float4* hs = (const float4*)(g_h + (size_t)src * EMB);
        float* ad = g_agg + (size_t)dst * EMB;
        float4 v0 = hs[lane * 2];
        float4 v1 = hs[lane * 2 + 1];
        red4(ad + lane * 8, v0);
        red4(ad + lane * 8 + 4, v1);
    }
}

// ---------------- kernel 5: Sinkhorn — SOR (omega=1.5) + polish + early exit ----------------
__device__ __forceinline__ void load_point(int node, int lane, float* p) {
    float dg = g_deg[node];
    float invd = 1.0f / fmaxf(dg, 1.0f);
    const float4* h4 = (const float4*)(g_h + (size_t)node * EMB);
    const float4* a4 = (const float4*)(g_agg + (size_t)node * EMB);
#pragma unroll
    for (int q = 0; q < 2; q++) {
        float4 hv = h4[lane * 2 + q];
        float4 av = a4[lane * 2 + q];
        p[q * 4 + 0] = fmaxf(fmaf(av.x, invd, hv.x), 0.f);
        p[q * 4 + 1] = fmaxf(fmaf(av.y, invd, hv.y), 0.f);
        p[q * 4 + 2] = fmaxf(fmaf(av.z, invd, hv.z), 0.f);
        p[q * 4 + 3] = fmaxf(fmaf(av.w, invd, hv.w), 0.f);
    }
}

// LSE update in K-scaled log2 domain (SHFL broadcast, f32 max, f16x2 exp+sum).
__device__ __forceinline__ float lse_update(float vK, const float* C) {
    float u[32];
    float m0 = -1e30f, m1 = -1e30f, m2 = -1e30f, m3 = -1e30f;
#pragma unroll
    for (int j = 0; j < 32; j += 4) {
        u[j]     = __shfl_sync(0xffffffffu, vK, j)     - C[j];     m0 = fmaxf(m0, u[j]);
        u[j + 1] = __shfl_sync(0xffffffffu, vK, j + 1) - C[j + 1]; m1 = fmaxf(m1, u[j + 1]);
        u[j + 2] = __shfl_sync(0xffffffffu, vK, j + 2) - C[j + 2]; m2 = fmaxf(m2, u[j + 2]);
        u[j + 3] = __shfl_sync(0xffffffffu, vK, j + 3) - C[j + 3]; m3 = fmaxf(m3, u[j + 3]);
    }
    float m = fmaxf(fmaxf(m0, m1), fmaxf(m2, m3));
    unsigned s0 = 0u, s1 = 0u, s2 = 0u, s3 = 0u;
#pragma unroll
    for (int j = 0; j < 32; j += 8) {
        s0 = hadd2u(s0, hexp2u(pack2(u[j]     - m, u[j + 1] - m)));
        s1 = hadd2u(s1, hexp2u(pack2(u[j + 2] - m, u[j + 3] - m)));
        s2 = hadd2u(s2, hexp2u(pack2(u[j + 4] - m, u[j + 5] - m)));
        s3 = hadd2u(s3, hexp2u(pack2(u[j + 6] - m, u[j + 7] - m)));
    }
    float S = hsum2u(hadd2u(hadd2u(s0, s1), hadd2u(s2, s3)));
    return 5.0f - m - flog2(S);   // C0*Kc = log2(32) = 5 exactly
}

__global__ __launch_bounds__(32) void sinkhorn_kernel() {
    __shared__ __align__(16) float Xsh[32][8];
    __shared__ __align__(16) float Ysh[32][8];
    int lane = threadIdx.x;
    int wg = blockIdx.x;

    int nx, ny;
    bool is_pair = (wg < N_PAIRS);
    if (is_pair) {
        nx = g_pair_idx[wg];
        ny = g_pair_idx[N_PAIRS + wg];
    } else {
        int s = wg - N_PAIRS;
        if (s >= g_nself) return;
        nx = ny = g_self_node[s];
    }

    float px[8], py[8];
    load_point(nx, lane, px);
    load_point(ny, lane, py);
#pragma unroll
    for (int k = 0; k < 8; k++) { Xsh[lane][k] = px[k]; Ysh[lane][k] = py[k]; }
    __syncwarp();

    const float Kc = 28.85390081777927f;   // log2(e)/eps
    float CK[32], CTK[32];
#pragma unroll
    for (int j = 0; j < 32; j++) {
        float d2 = 1e-12f, e2 = 1e-12f;
#pragma unroll
        for (int k = 0; k < 8; k++) {
            float dx = px[k] - Ysh[j][k]; d2 = fmaf(dx, dx, d2);
            float dy = py[k] - Xsh[j][k]; e2 = fmaf(dy, dy, e2);
        }
        CK[j] = __fsqrt_rn(d2) * Kc;
        CTK[j] = __fsqrt_rn(e2) * Kc;
    }

    // Over-relaxed Sinkhorn (same fixed point), omega=1.5, early exit at
    // TOL=0.22 K-units on relaxed deltas, then one PLAIN polish pair so the
    // returned (f,g) are mutually consistent (second-order-accurate value).
    // Measured error floor ~6e-5 is f16/polish-dominated, not TOL-dominated.
    const float TOL = 0.22f;
    const float OMEGA = 1.5f;
    float fK = 0.f, gK = 0.f;
#pragma unroll 1
    for (int it = 0; it < 50; it++) {
        float fp = fK, gp = gK;
        float fn = lse_update(gK, CK);
        fK = fmaf(OMEGA, fn - fK, fK);
        float gn = lse_update(fK, CTK);
        gK = fmaf(OMEGA, gn - gK, gK);
        bool conv = (fabsf(fK - fp) < TOL) && (fabsf(gK - gp) < TOL);
        if (__all_sync(0xffffffffu, conv)) break;
    }
    // plain polish pair
    fK = lse_update(gK, CK);
    gK = lse_update(fK, CTK);

    float sf = fK, sg = gK;
#pragma unroll
    for (int o = 16; o > 0; o >>= 1) {
        sf += __shfl_xor_sync(0xffffffffu, sf, o);
        sg += __shfl_xor_sync(0xffffffffu, sg, o);
    }
    if (lane == 0) {
        // (mean fK + mean gK) / Kc  =  (sf+sg) * eps*ln2 / 32
        float val = (sf + sg) * 0.001083042469624914f;
        if (is_pair) g_ot_pair[wg] = val;
        else g_ot_self[wg - N_PAIRS] = val;
    }
}

// ---------------- kernel 6: final distortion mean ----------------
__global__ void reduce_kernel(const float* __restrict__ gd, float* __restrict__ out) {
    __shared__ float sh[256];
    float s = 0.f;
    for (int b = threadIdx.x; b < N_PAIRS; b += 256) {
        int pa = g_pair_idx[b];
        int pb = g_pair_idx[N_PAIRS + b];
        float self_a = g_ot_self[g_self_slot[pa]];
        float self_b = g_ot_self[g_self_slot[pb]];
        float d = g_ot_pair[b] - 0.5f * (self_a + self_b);
        s += fabsf(d - gd[b]) / gd[b];
    }
    sh[threadIdx.x] = s;
    __syncthreads();
    for (int o = 128; o > 0; o >>= 1) {
        if (threadIdx.x < o) sh[threadIdx.x] += sh[threadIdx.x + o];
        __syncthreads();
    }
    if (threadIdx.x == 0) out[0] = sh[0] / (float)N_PAIRS;
}

// ---------------- launcher ----------------
extern "C" void kernel_launch(void* const* d_in, const int* in_sizes, int n_in,
                              void* d_out, int out_size) {
    const float* x = (const float*)d_in[0];
    const float* W = (const float*)d_in[1];
    const void* ei = d_in[2];
    const void* pairs = d_in[3];
    const float* gd = (const float*)d_in[4];
    float* out = (float*)d_out;

    zero_kernel<<<256, 256>>>();
    detect_kernel<<<32, 256>>>((const long long*)pairs);
    decode_pairs<<<(2 * N_PAIRS + 255) / 256, 256>>>(pairs);
    zero_agg_kernel<<<(N_NODES + 7) / 8, 256>>>();
    decode_edges<<<(N_EDGES + 255) / 256, 256>>>(ei);
    gemm_kernel<<<dim3((N_NODES + 63) / 64, EMB / 64), 256>>>(x, W);
    agg_kernel<<<512, 256>>>();
    sinkhorn_kernel<<<N_PAIRS + MAX_SELF, 32>>>();
    reduce_kernel<<<1, 256>>>(gd, out);
}